// round 2
// baseline (speedup 1.0000x reference)
#include <cuda_runtime.h>

#define NXc 64
#define NYc 64
#define NSPOTS 64
#define PATCH_HW 3
#define Pc 6
#define TPB 256

// LUT for Phi(u) = erf(u / (sqrt(2)*sigma)), u in [-4.5, 4.5]
#define LUT_N    1024
#define LUT_NE   1026          // N+2 entries (value + next-delta pairs, safe end)
#define LUT_U0   (-4.5f)
#define LUT_SCALE ((float)LUT_N / 9.0f)     // 113.777...
#define INV_ALPHA (0.768706f)  // 1/(sqrt(2)*0.92)

__device__ float2 g_lut[LUT_NE];

__global__ void lut_init_kernel()
{
    int i = blockIdx.x * blockDim.x + threadIdx.x;
    if (i < LUT_NE) {
        float u0 = LUT_U0 + (float)i       * (9.0f / LUT_N);
        float u1 = LUT_U0 + (float)(i + 1) * (9.0f / LUT_N);
        float a = erff(u0 * INV_ALPHA);
        float b = erff(u1 * INV_ALPHA);
        g_lut[i] = make_float2(a, b - a);
    }
}

__device__ __forceinline__ float lut_phi(const float2* __restrict__ lut, float u)
{
    float f  = fmaf(u, LUT_SCALE, -LUT_U0 * LUT_SCALE);  // (u - U0)*scale, >= 0
    int   i  = __float2int_rd(f);
    float fr = f - (float)i;
    float2 e = lut[i];
    return fmaf(e.y, fr, e.x);
}

__global__ __launch_bounds__(TPB) void spot_render_kernel(
    const float* __restrict__ z, float* __restrict__ out)
{
    __shared__ float  img[NXc * NYc];          // 16 KB
    __shared__ float  slx[NSPOTS * Pc];        // includes I0*0.5*valid factor
    __shared__ float  sly[NSPOTS * Pc];        // includes 0.5*valid factor
    __shared__ int    spxy[NSPOTS];            // packed clamped px | py<<8
    __shared__ float  sx0p[NSPOTS];
    __shared__ float  sy0p[NSPOTS];
    __shared__ float  sval[NSPOTS];            // 1.0 valid / 0.0 invalid
    __shared__ float2 lut[LUT_NE];             // ~8.2 KB

    const int b   = blockIdx.x;
    const int tid = threadIdx.x;

    // ---- prologue (pre-sync1): zero image, copy LUT, per-spot meta ----
    {
        float4* im4 = reinterpret_cast<float4*>(img);
        #pragma unroll
        for (int i = tid; i < (NXc * NYc) / 4; i += TPB)
            im4[i] = make_float4(0.f, 0.f, 0.f, 0.f);
    }
    #pragma unroll
    for (int i = tid; i < LUT_NE; i += TPB)
        lut[i] = g_lut[i];

    if (tid < NSPOTS) {
        const int s = tid;
        const float* zrow = z + (size_t)b * (2 * NSPOTS);
        const float x0 = zrow[s];
        const float y0 = zrow[NSPOTS + s];
        const int px = __float2int_rn(x0) - PATCH_HW;   // round-half-even == jnp.round
        const int py = __float2int_rn(y0) - PATCH_HW;
        const bool valid = (px >= 0) & (px < NXc - Pc) & (py >= 0) & (py < NYc - Pc);
        const int pxc = valid ? px : 0;
        const int pyc = valid ? py : 0;
        spxy[s] = pxc | (pyc << 8);
        sx0p[s] = x0 - (float)px;   // raw px: keeps LUT arg in range; lam zeroed below
        sy0p[s] = y0 - (float)py;
        sval[s] = valid ? 1.0f : 0.0f;
    }
    __syncthreads();

    // ---- phase B: 768 lambda values via LUT ----
    // i = jj*64 + s, jj in [0,12): jj<6 -> x-dim t=jj, else y-dim t=jj-6
    #pragma unroll
    for (int k = 0; k < 3; k++) {
        const int i  = k * TPB + tid;
        const int s  = i & 63;
        const int jj = i >> 6;
        const bool isx = (jj < Pc);
        const float t  = (float)(isx ? jj : jj - Pc);
        const float t0 = isx ? sx0p[s] : sy0p[s];
        const float a  = t + 0.5f - t0;
        const float lam = (lut_phi(lut, a) - lut_phi(lut, a - 1.0f)) * sval[s];
        if (isx) slx[s * Pc + jj]        = lam * 500.0f;   // I0 * 0.5
        else     sly[s * Pc + (jj - Pc)] = lam * 0.5f;
    }
    __syncthreads();

    // ---- phase C: scatter. item i = (s, ix), 384 items, 6 atomics each ----
    {
        const int i = tid;            // first 256 items
        const int s  = i / Pc;
        const int ix = i - s * Pc;
        const int meta = spxy[s];
        const float lx = slx[i];      // address == 4*i, layout trick
        const float2 ly01 = *reinterpret_cast<const float2*>(&sly[s * Pc + 0]);
        const float2 ly23 = *reinterpret_cast<const float2*>(&sly[s * Pc + 2]);
        const float2 ly45 = *reinterpret_cast<const float2*>(&sly[s * Pc + 4]);
        float* row = &img[(((meta & 255) + ix) << 6) + (meta >> 8)];
        atomicAdd(row + 0, lx * ly01.x);
        atomicAdd(row + 1, lx * ly01.y);
        atomicAdd(row + 2, lx * ly23.x);
        atomicAdd(row + 3, lx * ly23.y);
        atomicAdd(row + 4, lx * ly45.x);
        atomicAdd(row + 5, lx * ly45.y);
    }
    if (tid < NSPOTS * Pc - TPB) {    // remaining 128 items
        const int i = TPB + tid;
        const int s  = i / Pc;
        const int ix = i - s * Pc;
        const int meta = spxy[s];
        const float lx = slx[i];
        const float2 ly01 = *reinterpret_cast<const float2*>(&sly[s * Pc + 0]);
        const float2 ly23 = *reinterpret_cast<const float2*>(&sly[s * Pc + 2]);
        const float2 ly45 = *reinterpret_cast<const float2*>(&sly[s * Pc + 4]);
        float* row = &img[(((meta & 255) + ix) << 6) + (meta >> 8)];
        atomicAdd(row + 0, lx * ly01.x);
        atomicAdd(row + 1, lx * ly01.y);
        atomicAdd(row + 2, lx * ly23.x);
        atomicAdd(row + 3, lx * ly23.y);
        atomicAdd(row + 4, lx * ly45.x);
        atomicAdd(row + 5, lx * ly45.y);
    }
    __syncthreads();

    // ---- phase D: coalesced float4 writeback ----
    float4* o = reinterpret_cast<float4*>(out + (size_t)b * (NXc * NYc));
    const float4* im = reinterpret_cast<const float4*>(img);
    #pragma unroll
    for (int i = tid; i < (NXc * NYc) / 4; i += TPB)
        o[i] = im[i];
}

extern "C" void kernel_launch(void* const* d_in, const int* in_sizes, int n_in,
                              void* d_out, int out_size)
{
    const float* z = (const float*)d_in[0];
    float* out = (float*)d_out;
    const int B = in_sizes[0] / (2 * NSPOTS);   // 8192
    lut_init_kernel<<<(LUT_NE + 255) / 256, 256>>>();
    spot_render_kernel<<<B, TPB>>>(z, out);
}

// round 3
// speedup vs baseline: 1.9397x; 1.9397x over previous
#include <cuda_runtime.h>

#define NXc 64
#define NYc 64
#define NSPOTS 64
#define PATCH_HW 3
#define Pc 6
#define TPB 256

// swizzled shared-image address for pixel (r, c): rotate row r by 4*r columns
__device__ __forceinline__ int sw_addr(int r, int c) {
    return (r << 6) + ((c + (r << 2)) & 63);
}

__global__ __launch_bounds__(TPB) void spot_render_kernel(
    const float* __restrict__ z, float* __restrict__ out)
{
    __shared__ float img[NXc * NYc];     // 16 KB, row-rotated layout
    __shared__ float slx[NSPOTS * Pc];   // I0*0.5*lam_x*valid
    __shared__ float sly[NSPOTS * Pc];   // 0.5*lam_y*valid
    __shared__ int   spxy[NSPOTS];       // clamped px | py<<8
    __shared__ float sx0p[NSPOTS];
    __shared__ float sy0p[NSPOTS];
    __shared__ float sval[NSPOTS];

    const int b    = blockIdx.x;
    const int tid  = threadIdx.x;
    const int lane = tid & 31;
    const int w    = tid >> 5;

    const float inv_alpha = 0.76870611479f;  // 1/(sqrt(2)*0.92)

    // ---- prologue: zero image (float4), per-spot meta ----
    {
        float4* im4 = reinterpret_cast<float4*>(img);
        #pragma unroll
        for (int i = tid; i < (NXc * NYc) / 4; i += TPB)
            im4[i] = make_float4(0.f, 0.f, 0.f, 0.f);
    }
    if (tid < NSPOTS) {
        const int s = tid;
        const float* zrow = z + (size_t)b * (2 * NSPOTS);
        const float x0 = __ldg(zrow + s);
        const float y0 = __ldg(zrow + NSPOTS + s);
        const int px = __float2int_rn(x0) - PATCH_HW;   // round-half-even == jnp.round
        const int py = __float2int_rn(y0) - PATCH_HW;
        const bool valid = (px >= 0) & (px < NXc - Pc) & (py >= 0) & (py < NYc - Pc);
        spxy[s] = (valid ? px : 0) | ((valid ? py : 0) << 8);
        sx0p[s] = x0 - (float)px;
        sy0p[s] = y0 - (float)py;
        sval[s] = valid ? 1.0f : 0.0f;
    }
    __syncthreads();

    // ---- phase B: 768 lambda values, direct erff ----
    // i = jj*64 + s : jj<6 -> x-dim (t=jj), else y-dim (t=jj-6)
    #pragma unroll
    for (int k = 0; k < 3; k++) {
        const int i  = k * TPB + tid;
        const int s  = i & 63;
        const int jj = i >> 6;
        const bool isx = (jj < Pc);
        const float t  = (float)(isx ? jj : jj - Pc);
        const float t0 = isx ? sx0p[s] : sy0p[s];
        const float a  = (t + 0.5f - t0) * inv_alpha;
        const float dx = erff(a) - erff(a - inv_alpha);
        const float lam = dx * sval[s] * (isx ? 500.0f : 0.5f);  // fold I0*0.5 / 0.5
        if (isx) slx[s * Pc + jj]        = lam;
        else     sly[s * Pc + (jj - Pc)] = lam;
    }
    __syncthreads();

    // ---- phase C: warp-per-spot scatter, swizzled atomics ----
    // warp w handles spots s = w*8 .. w*8+7; lanes cover pixels 0..31, then 32..35
    #pragma unroll
    for (int k = 0; k < NSPOTS / 8; k++) {
        const int s    = w * 8 + k;
        const int meta = spxy[s];                 // broadcast
        const int row0 = meta & 255;
        const int col0 = meta >> 8;
        {
            const int p  = lane;                  // 0..31
            const int ix = (p * 171) >> 10;       // p/6 for p<=35
            const int iy = p - ix * Pc;
            const float v = slx[s * Pc + ix] * sly[s * Pc + iy];  // 1-wf multicast LDS
            atomicAdd(&img[sw_addr(row0 + ix, col0 + iy)], v);
        }
        if (lane < 4) {
            const int p  = 32 + lane;             // 32..35 -> ix=5, iy=2..5
            const int iy = p - 30;
            const float v = slx[s * Pc + 5] * sly[s * Pc + iy];
            atomicAdd(&img[sw_addr(row0 + 5, col0 + iy)], v);
        }
    }
    __syncthreads();

    // ---- phase D: un-swizzle + coalesced float4 writeback ----
    // thread handles (r, cg): out float4 idx r*16+cg  <-  img float4 idx r*16+((cg+r)&15)
    float4* o = reinterpret_cast<float4*>(out + (size_t)b * (NXc * NYc));
    const float4* im4 = reinterpret_cast<const float4*>(img);
    #pragma unroll
    for (int k = 0; k < (NXc * NYc) / (4 * TPB); k++) {   // 4 iters
        const int i  = k * TPB + tid;
        const int r  = i >> 4;
        const int cg = i & 15;
        o[i] = im4[(r << 4) + ((cg + r) & 15)];
    }
}

extern "C" void kernel_launch(void* const* d_in, const int* in_sizes, int n_in,
                              void* d_out, int out_size)
{
    const float* z = (const float*)d_in[0];
    float* out = (float*)d_out;
    const int B = in_sizes[0] / (2 * NSPOTS);   // 8192
    spot_render_kernel<<<B, TPB>>>(z, out);
}